// round 5
// baseline (speedup 1.0000x reference)
#include <cuda_runtime.h>
#include <math.h>
#include <float.h>

#define HH 496
#define WW 496
#define NC 9          // sigma x lambda combos
#define NT 8          // thetas
#define NW 31         // windows per dim (496/16)
#define NWIN (NW*NW)  // 961
#define NCOEF (NT*NC*25)

// ---- scratch (static device globals; no allocation) ----
__device__ float gCoef[NCOEF];          // [t][c][25]
__device__ float gOut[NC*HH*WW];        // conv+max result, 8.86 MB
__device__ float gPartial[NC*NWIN];     // per-block channel sums
__device__ float gThr5[NC];             // mean*5 per channel

__device__ __constant__ float dThetas[8] = {
    0.39269908169872414f, 0.7853981633974483f, 1.1780972450961724f,
    1.5707963267948966f,  1.9634954084936207f, 2.356194490192345f,
    2.748893571891069f,   3.141592653589793f
};

// ---- packed f32x2 helpers (Blackwell sm_103a) ----
__device__ __forceinline__ unsigned long long pk2(float lo, float hi) {
    unsigned long long r;
    asm("mov.b64 %0, {%1, %2};" : "=l"(r) : "f"(lo), "f"(hi));
    return r;
}
__device__ __forceinline__ void upk2(float& lo, float& hi, unsigned long long v) {
    asm("mov.b64 {%0, %1}, %2;" : "=f"(lo), "=f"(hi) : "l"(v));
}
__device__ __forceinline__ unsigned long long ffma2(unsigned long long a,
                                                    unsigned long long b,
                                                    unsigned long long c) {
    unsigned long long d;
    asm("fma.rn.f32x2 %0, %1, %2, %3;" : "=l"(d) : "l"(a), "l"(b), "l"(c));
    return d;
}

// ============ Kernel 1: Gabor bank ============
__global__ void gabor_kernel(const float* __restrict__ sigmas,
                             const float* __restrict__ lambdas) {
    int i = blockIdx.x * blockDim.x + threadIdx.x;
    if (i >= NCOEF) return;
    int k = i % 25;
    int c = (i / 25) % NC;
    int t = i / (25 * NC);
    int s = c / 3, l = c % 3;
    float sig = sigmas[s];
    float lam = lambdas[l];
    float th  = dThetas[t];
    int ky = k / 5, kx = k % 5;
    float y = (float)ky - 2.0f;
    float x = (float)kx - 2.0f;
    float st = sinf(th), ct = cosf(th);
    float yth = -x * st + y * ct;
    float xth =  x * ct + y * st;
    float sx = sig;          // sigma_x
    float sy = 2.0f * sig;   // sigma_y = sigma/gamma, gamma=0.5
    float e = expf(-0.5f * (xth*xth/(sx*sx) + yth*yth/(sy*sy)));
    float g = e * cosf(6.283185307179586f * xth / lam + 1.5707963267948966f);
    gCoef[(t * NC + c) * 25 + k] = g;
}

// ============ Kernel 2: conv (72 filters, packed f32x2 FMA) + max + sums ====
// 31x31 blocks of 64 threads; 16x16 output tile; thread = 4 horizontal pixels.
// Coefficients stored duplicated (w,w) in smem -> 1 LDS.64 feeds 2 FFMA2 (4 MACs).
__global__ void __launch_bounds__(64)
conv_kernel(const float* __restrict__ img) {
    __shared__ float sIn[20 * 20];
    __shared__ unsigned long long sCf2[NCOEF];   // duplicated (w,w)
    __shared__ float sSum[NC * 64];

    int tid = threadIdx.x;
    int bx = blockIdx.x, by = blockIdx.y;
    int r0 = by * 16 - 2, c0 = bx * 16 - 2;

    // halo'd input tile (zero pad)
    for (int i = tid; i < 400; i += 64) {
        int r = i / 20, cc = i % 20;
        int gr = r0 + r, gc = c0 + cc;
        sIn[i] = (gr >= 0 && gr < HH && gc >= 0 && gc < WW) ? img[gr * WW + gc] : 0.0f;
    }
    for (int i = tid; i < NCOEF; i += 64) {
        float w = gCoef[i];
        sCf2[i] = pk2(w, w);
    }
    __syncthreads();

    int ty = tid >> 2;            // 0..15
    int tx = (tid & 3) * 4;       // 0,4,8,12

    // pre-packed adjacent-pixel pairs: P[r][s] = (vin[r][s], vin[r][s+1])
    unsigned long long P[5][7];
    #pragma unroll
    for (int r = 0; r < 5; r++) {
        float row[8];
        #pragma unroll
        for (int cc = 0; cc < 8; cc++)
            row[cc] = sIn[(ty + r) * 20 + tx + cc];
        #pragma unroll
        for (int s = 0; s < 7; s++)
            P[r][s] = pk2(row[s], row[s + 1]);
    }

    float vmax[4][NC];
    #pragma unroll
    for (int p = 0; p < 4; p++)
        #pragma unroll
        for (int c = 0; c < NC; c++) vmax[p][c] = -FLT_MAX;

    for (int t = 0; t < NT; t++) {
        const unsigned long long* cf = sCf2 + t * NC * 25;
        #pragma unroll
        for (int c = 0; c < NC; c++) {
            unsigned long long acc01 = 0ull, acc23 = 0ull;
            #pragma unroll
            for (int k = 0; k < 25; k++) {
                unsigned long long w = cf[c * 25 + k];
                acc01 = ffma2(P[k / 5][k % 5],     w, acc01);
                acc23 = ffma2(P[k / 5][k % 5 + 2], w, acc23);
            }
            float a0, a1, a2, a3;
            upk2(a0, a1, acc01);
            upk2(a2, a3, acc23);
            vmax[0][c] = fmaxf(vmax[0][c], a0);
            vmax[1][c] = fmaxf(vmax[1][c], a1);
            vmax[2][c] = fmaxf(vmax[2][c], a2);
            vmax[3][c] = fmaxf(vmax[3][c], a3);
        }
    }

    int gy = by * 16 + ty;
    int gx = bx * 16 + tx;
    #pragma unroll
    for (int c = 0; c < NC; c++) {
        float4 o = make_float4(vmax[0][c], vmax[1][c], vmax[2][c], vmax[3][c]);
        *(float4*)&gOut[c * HH * WW + gy * WW + gx] = o;
        sSum[c * 64 + tid] = vmax[0][c] + vmax[1][c] + vmax[2][c] + vmax[3][c];
    }
    __syncthreads();
    // deterministic tree reduce (no fp atomics!)
    for (int off = 32; off >= 1; off >>= 1) {
        if (tid < off) {
            #pragma unroll
            for (int c = 0; c < NC; c++)
                sSum[c * 64 + tid] += sSum[c * 64 + tid + off];
        }
        __syncthreads();
    }
    if (tid == 0) {
        int b = by * NW + bx;
        #pragma unroll
        for (int c = 0; c < NC; c++)
            gPartial[c * NWIN + b] = sSum[c * 64];
    }
}

// ============ Kernel 3: deterministic mean -> thr5 (one block per channel) ==
__global__ void mean_kernel() {
    __shared__ float sh[128];
    int c = blockIdx.x;
    int tid = threadIdx.x;
    float s = 0.0f;
    for (int i = tid; i < NWIN; i += 128) s += gPartial[c * NWIN + i];
    sh[tid] = s;
    __syncthreads();
    for (int off = 64; off >= 32; off >>= 1) {
        if (tid < off) sh[tid] += sh[tid + off];
        __syncthreads();
    }
    if (tid < 32) {
        s = sh[tid];
        #pragma unroll
        for (int off = 16; off; off >>= 1)
            s += __shfl_down_sync(0xffffffff, s, off);
        if (tid == 0)
            gThr5[c] = (s / (float)(HH * WW)) * 5.0f;
    }
}

// ============ Kernel 4: fused argmax + patch extraction ============
// One block per window w (961 blocks x 256 threads). Each thread holds 4
// horizontal patch elements for all 9 channels (v[9][4]).
// The 16x16 detection window is the patch's central rows/cols 8..23, so the
// thresholded-argmax is computed from data already in registers.
__global__ void __launch_bounds__(256)
patch_kernel(float* __restrict__ dst) {
    __shared__ float sB[NC][8];
    __shared__ int   sI[NC][8];
    __shared__ unsigned sNzW[8];
    __shared__ int   sFlag[NC];
    __shared__ unsigned sOutMask;   // bit c: write channel c

    int w = blockIdx.x;
    int tid = threadIdx.x;
    int lane = tid & 31, wid = tid >> 5;
    int wr = (w / NW) * 16 - 8;     // top row of 32x32 patch in image coords
    int wc = (w % NW) * 16 - 8;
    int i  = tid >> 3;              // patch row 0..31
    int j0 = (tid & 7) * 4;         // patch col base
    int rr = wr + i;
    bool rok = (rr >= 0 && rr < HH);
    bool inwin = (i >= 8 && i < 24 && j0 >= 8 && j0 < 24);

    float v[NC][4];
    unsigned nzm = 0;

    #pragma unroll
    for (int c = 0; c < NC; c++) {
        const float* o = gOut + c * HH * WW;
        float thr5 = gThr5[c];
        bool nz = false;
        #pragma unroll
        for (int e = 0; e < 4; e++) {
            int cc = wc + j0 + e;
            float val = (rok && cc >= 0 && cc < WW) ? o[rr * WW + cc] : 0.0f;
            v[c][e] = val;
            nz |= (val != 0.0f);
        }
        if (nz) nzm |= (1u << c);

        // thresholded first-occurrence argmax over central 16x16 window
        float best = -FLT_MAX;
        int bidx = 256;
        if (inwin) {
            #pragma unroll
            for (int e = 0; e < 4; e++) {
                float val = v[c][e];
                float tv = (val > thr5) ? val : 0.0f;
                int f = (i - 8) * 16 + (j0 - 8 + e);   // ascending within thread
                if (tv > best) { best = tv; bidx = f; } // strict > keeps first
            }
        }
        #pragma unroll
        for (int off = 16; off; off >>= 1) {
            float ov = __shfl_xor_sync(0xffffffff, best, off);
            int   oi = __shfl_xor_sync(0xffffffff, bidx, off);
            if (ov > best || (ov == best && oi < bidx)) { best = ov; bidx = oi; }
        }
        if (lane == 0) { sB[c][wid] = best; sI[c][wid] = bidx; }
    }

    // per-warp OR of nonzero masks
    unsigned wnz = __reduce_or_sync(0xffffffff, nzm);
    if (lane == 0) sNzW[wid] = wnz;
    __syncthreads();

    if (tid < NC) {
        float best = -FLT_MAX; int bidx = 256;
        #pragma unroll
        for (int k = 0; k < 8; k++) {
            float ov = sB[tid][k]; int oi = sI[tid][k];
            if (ov > best || (ov == best && oi < bidx)) { best = ov; bidx = oi; }
        }
        sFlag[tid] = (bidx == 128);
    }
    __syncthreads();
    if (tid == 0) {
        int valid = 0;
        unsigned nzAll = 0;
        #pragma unroll
        for (int k = 0; k < NC; k++) valid |= sFlag[k];
        #pragma unroll
        for (int k = 0; k < 8; k++) nzAll |= sNzW[k];
        sOutMask = valid ? nzAll : 0u;
    }
    __syncthreads();

    unsigned om = sOutMask;
    #pragma unroll
    for (int c = 0; c < NC; c++) {
        float m = ((om >> c) & 1u) ? 1.0f : 0.0f;
        float4 o = make_float4(v[c][0] * m, v[c][1] * m, v[c][2] * m, v[c][3] * m);
        ((float4*)dst)[(c * NWIN + w) * 256 + tid] = o;
    }
}

// ============ launcher ============
extern "C" void kernel_launch(void* const* d_in, const int* in_sizes, int n_in,
                              void* d_out, int out_size) {
    const float* img     = (const float*)d_in[0];
    const float* sigmas  = (const float*)d_in[1];
    const float* lambdas = (const float*)d_in[2];
    float* out = (float*)d_out;

    gabor_kernel<<<(NCOEF + 255) / 256, 256>>>(sigmas, lambdas);
    conv_kernel<<<dim3(NW, NW), 64>>>(img);
    mean_kernel<<<NC, 128>>>();
    patch_kernel<<<NWIN, 256>>>(out);
}